// round 5
// baseline (speedup 1.0000x reference)
#include <cuda_runtime.h>
#include <cstdint>

#define HH   480
#define WW   640
#define DIMC 32
#define NB   8
#define HWSZ (HH * WW)
#define NPIX (NB * HWSZ)   // 2,457,600 sites

// Scratch: per-site feature sums in [site, DIM] layout (contiguous per event)
// and per-site hit counts. __device__ globals per allocation rules.
__device__ float g_sum[(size_t)NPIX * DIMC];   // ~314.6 MB
__device__ float g_cnt[NPIX];                  // ~9.8 MB
__device__ int   g_off[NB];                    // canonical int32 offsets

// Normalize offsets to int32 regardless of whether the harness stored them
// as int64 (JAX x64 enabled) or int32 (default JAX downcast).
// int64 little-endian: 32-bit words are [v0, 0, v1, 0, ...] (values ~2e6 << 2^31)
// int32:               words are [v0, v1, ...] with v1 = 500000 != 0.
__global__ void prep_offsets_kernel(const int* __restrict__ o32)
{
    bool is64 = (o32[1] == 0);
#pragma unroll
    for (int i = 0; i < NB; i++)
        g_off[i] = is64 ? o32[2 * i] : o32[i];
}

// 8 threads per event; each thread does one float4 vector-RED (channels part*4..+3).
__global__ void scatter_kernel(const float* __restrict__ events,
                               const float* __restrict__ features,
                               int n)
{
    int t = blockIdx.x * blockDim.x + threadIdx.x;
    int e = t >> 3;
    if (e >= n) return;
    int part = t & 7;

    // broadcast loads (all 8 lanes of an event read the same addresses)
    float ex = __ldg(events + 2 * e);
    float ey = __ldg(events + 2 * e + 1);

    // jnp.round == round-half-even == __float2int_rn; then clip
    int x = __float2int_rn(ex * (float)WW);
    int y = __float2int_rn(ey * (float)HH);
    x = min(max(x, 0), WW - 1);
    y = min(max(y, 0), HH - 1);

    // searchsorted(offsets, e, side='right') = count of offsets <= e
    int b = 0;
#pragma unroll
    for (int i = 0; i < NB; i++)
        b += (e >= g_off[i]) ? 1 : 0;

    int pix = (b * HH + y) * WW + x;

    // fully coalesced: consecutive threads read consecutive 16B
    float4 f = __ldg((const float4*)features + (size_t)e * 8 + part);

    float* dst = g_sum + (size_t)pix * DIMC + part * 4;
    asm volatile("red.global.add.v4.f32 [%0], {%1, %2, %3, %4};"
                 :: "l"(dst), "f"(f.x), "f"(f.y), "f"(f.z), "f"(f.w)
                 : "memory");
    if (part == 0) {
        asm volatile("red.global.add.f32 [%0], %1;"
                     :: "l"(g_cnt + pix), "f"(1.0f)
                     : "memory");
    }
}

// One block per 32 consecutive sites: read [site,32] coalesced, normalize,
// transpose via smem, write [B, D, H, W] as coalesced float4.
// W=640 and H*W are multiples of 32, so a 32-site tile never crosses a row/batch.
__global__ void finalize_kernel(float* __restrict__ out)
{
    __shared__ float s[32][33];   // [site_in_tile][channel], padded
    __shared__ float sinv[32];

    int tid  = threadIdx.x;            // 0..255
    int pix0 = blockIdx.x * 32;

    // Load phase: thread tid loads float4 covering site tid>>3, channels (tid&7)*4..+3
    {
        int p  = tid >> 3;
        int c0 = (tid & 7) * 4;
        float4 v = __ldg((const float4*)g_sum + (size_t)pix0 * 8 + tid);
        s[p][c0 + 0] = v.x;
        s[p][c0 + 1] = v.y;
        s[p][c0 + 2] = v.z;
        s[p][c0 + 3] = v.w;
    }
    if (tid < 32) {
        float c = g_cnt[pix0 + tid];
        sinv[tid] = 1.0f / fmaxf(c, 1.0f);
    }
    __syncthreads();

    // Write phase: thread tid writes channel d = tid>>3, sites (tid&7)*4..+3 (one float4)
    int d   = tid >> 3;
    int px0 = (tid & 7) * 4;
    float4 o;
    o.x = s[px0 + 0][d] * sinv[px0 + 0];
    o.y = s[px0 + 1][d] * sinv[px0 + 1];
    o.z = s[px0 + 2][d] * sinv[px0 + 2];
    o.w = s[px0 + 3][d] * sinv[px0 + 3];

    int bb  = pix0 / HWSZ;
    int rem = pix0 - bb * HWSZ;        // in-plane offset, multiple of 32
    float4* orow = (float4*)(out + (size_t)bb * DIMC * HWSZ + (size_t)d * HWSZ + rem);
    orow[tid & 7] = o;
}

extern "C" void kernel_launch(void* const* d_in, const int* in_sizes, int n_in,
                              void* d_out, int out_size)
{
    const float* events   = (const float*)d_in[0];
    const float* features = (const float*)d_in[1];
    const int*   offs_raw = (const int*)d_in[2];
    int n = in_sizes[0] / 2;

    void* sum_ptr = nullptr;
    void* cnt_ptr = nullptr;
    cudaGetSymbolAddress(&sum_ptr, g_sum);
    cudaGetSymbolAddress(&cnt_ptr, g_cnt);
    cudaMemsetAsync(sum_ptr, 0, (size_t)NPIX * DIMC * sizeof(float), 0);
    cudaMemsetAsync(cnt_ptr, 0, (size_t)NPIX * sizeof(float), 0);

    prep_offsets_kernel<<<1, 1>>>(offs_raw);

    const int threads = 256;
    int total  = n * 8;                         // 8 threads per event
    int blocks = (total + threads - 1) / threads;
    scatter_kernel<<<blocks, threads>>>(events, features, n);

    finalize_kernel<<<NPIX / 32, 256>>>((float*)d_out);
}